// round 3
// baseline (speedup 1.0000x reference)
#include <cuda_runtime.h>

// SurfEval: NURBS surface evaluation. B=8, M=N=64, P=Q=3, GRID=512, DIM=3.
// Block = (g, b-quad): each block handles one u-grid line g for FOUR batches.
// Stage A: u-contracted rows Su[4][64] (float4) in smem.
// Stage B: each thread owns 4 consecutive h points; computes the 5-tap
// span-shifted Nv weights ONCE, then loops over the 4 batches
// (5 LDS.128 + dots + 3 aligned STG.128 per batch).

#define GRID_N 512
#define MCTRL 64
#define NCTRL 64
#define BQ 4            // batches per block

__global__ __launch_bounds__(128) void surf_eval_kernel(
    const float4* __restrict__ ctrl,   // (B, 64, 64) float4
    const int*    __restrict__ uspan,  // (512)
    const int4*   __restrict__ vspan4, // (512) ints viewed as (128) int4
    const float4* __restrict__ Nu,     // (512) float4
    const float4* __restrict__ Nv,     // (512) float4
    float4*       __restrict__ out)    // (B*512*512*3)/4 float4
{
    __shared__ float4 Su[BQ][NCTRL + 1];   // +1: q-window may touch index 64 (zeroed)

    const int g  = blockIdx.x;
    const int b0 = blockIdx.y * BQ;
    const int t  = threadIdx.x;

    // ---- Stage A: Su[bb][n] = sum_r Nu[g,r] * ctrl[b0+bb, us-3+r, n, :] ----
    {
        const int   us = __ldg(uspan + g);
        const float4 nu = __ldg(Nu + g);
        const int n  = t & 63;
        const int bl = t >> 6;             // 0..1
#pragma unroll
        for (int p = 0; p < 2; ++p) {
            const int bb = bl + 2 * p;     // 0..3
            const float4* base = ctrl + ((size_t)(b0 + bb) * MCTRL + (size_t)(us - 3)) * NCTRL + n;
            const float4 c0 = __ldg(base);
            const float4 c1 = __ldg(base + NCTRL);
            const float4 c2 = __ldg(base + 2 * NCTRL);
            const float4 c3 = __ldg(base + 3 * NCTRL);
            float4 a;
            a.x = nu.x * c0.x + nu.y * c1.x + nu.z * c2.x + nu.w * c3.x;
            a.y = nu.x * c0.y + nu.y * c1.y + nu.z * c2.y + nu.w * c3.y;
            a.z = nu.x * c0.z + nu.y * c1.z + nu.z * c2.z + nu.w * c3.z;
            a.w = nu.x * c0.w + nu.y * c1.w + nu.z * c2.w + nu.w * c3.w;
            Su[bb][n] = a;
        }
        if (t >= 124) Su[t - 124][NCTRL] = make_float4(0.f, 0.f, 0.f, 0.f);
    }
    __syncthreads();

    // ---- Stage B ----
    const int h0 = t << 2;
    const int4 vsv = __ldg(vspan4 + t);
    const int vs_arr[4] = {vsv.x, vsv.y, vsv.z, vsv.w};
    const int j0 = vsv.x - 3;

    // 5-tap weights per h point (span delta vs first point is 0 or 1).
    float w[4][5];
#pragma unroll
    for (int k = 0; k < 4; ++k) {
        const float4 nv = __ldg(Nv + h0 + k);
        const bool s = (vs_arr[k] != vsv.x);
        w[k][0] = s ? 0.0f : nv.x;
        w[k][1] = s ? nv.x : nv.y;
        w[k][2] = s ? nv.y : nv.z;
        w[k][3] = s ? nv.z : nv.w;
        w[k][4] = s ? nv.w : 0.0f;
    }

    // Output base for this thread within a (b,g) row: float4 index t*3.
    float4* orow = out + ((size_t)(b0 * GRID_N + g) * GRID_N * 3) / 4 + (size_t)t * 3;
    const size_t brow_stride = (size_t)GRID_N * GRID_N * 3 / 4;  // float4 per batch

#pragma unroll
    for (int bb = 0; bb < BQ; ++bb) {
        const float4* SuB = Su[bb];
        const float4 q0 = SuB[j0];
        const float4 q1 = SuB[j0 + 1];
        const float4 q2 = SuB[j0 + 2];
        const float4 q3 = SuB[j0 + 3];
        const float4 q4 = SuB[j0 + 4];

        float r[12];
#pragma unroll
        for (int k = 0; k < 4; ++k) {
            const float X = w[k][0] * q0.x + w[k][1] * q1.x + w[k][2] * q2.x + w[k][3] * q3.x + w[k][4] * q4.x;
            const float Y = w[k][0] * q0.y + w[k][1] * q1.y + w[k][2] * q2.y + w[k][3] * q3.y + w[k][4] * q4.y;
            const float Z = w[k][0] * q0.z + w[k][1] * q1.z + w[k][2] * q2.z + w[k][3] * q3.z + w[k][4] * q4.z;
            const float W = w[k][0] * q0.w + w[k][1] * q1.w + w[k][2] * q2.w + w[k][3] * q3.w + w[k][4] * q4.w;
            const float inv = __fdividef(1.0f, W);
            r[k * 3 + 0] = X * inv;
            r[k * 3 + 1] = Y * inv;
            r[k * 3 + 2] = Z * inv;
        }

        float4* o = orow + (size_t)bb * brow_stride;
        o[0] = make_float4(r[0], r[1], r[2], r[3]);
        o[1] = make_float4(r[4], r[5], r[6], r[7]);
        o[2] = make_float4(r[8], r[9], r[10], r[11]);
    }
}

extern "C" void kernel_launch(void* const* d_in, const int* in_sizes, int n_in,
                              void* d_out, int out_size) {
    const float4* ctrl   = (const float4*)d_in[0];
    const int*    uspan  = (const int*)d_in[1];
    const int4*   vspan4 = (const int4*)d_in[2];
    const float4* Nu     = (const float4*)d_in[3];
    const float4* Nv     = (const float4*)d_in[4];

    const int B = in_sizes[0] / (MCTRL * NCTRL * 4);  // ctrl_pts elements = B*64*64*4

    dim3 grid(GRID_N, B / BQ);
    surf_eval_kernel<<<grid, 128>>>(ctrl, uspan, vspan4, Nu, Nv, (float4*)d_out);
}

// round 4
// speedup vs baseline: 1.0466x; 1.0466x over previous
#include <cuda_runtime.h>

// SurfEval: NURBS surface evaluation. B=8, M=N=64, P=Q=3, GRID=512, DIM=3.
// Block = (g, b-quad). Stage A: u-contracted rows Su[4][64] (float4) in smem.
// Stage B: each thread owns 4 consecutive h points; 5-tap span-shifted window
// shared across the 4 points and reused across 4 batches.
// __launch_bounds__(128, 8) pins regs <= 64 so 8 CTAs/SM -> 32 warps/SM and the
// whole 1024-block grid fits in ONE wave (8 x 148 = 1184 >= 1024).

#define GRID_N 512
#define MCTRL 64
#define NCTRL 64
#define BQ 4            // batches per block

__global__ __launch_bounds__(128, 8) void surf_eval_kernel(
    const float4* __restrict__ ctrl,   // (B, 64, 64) float4
    const int*    __restrict__ uspan,  // (512)
    const int4*   __restrict__ vspan4, // (512) ints viewed as (128) int4
    const float4* __restrict__ Nu,     // (512) float4
    const float4* __restrict__ Nv,     // (512) float4
    float4*       __restrict__ out)    // (B*512*512*3)/4 float4
{
    __shared__ float4 Su[BQ][NCTRL + 1];   // +1: q-window may touch index 64 (zeroed)

    const int g  = blockIdx.x;
    const int b0 = blockIdx.y * BQ;
    const int t  = threadIdx.x;

    // ---- Stage A: Su[bb][n] = sum_r Nu[g,r] * ctrl[b0+bb, us-3+r, n, :] ----
    {
        const int   us = __ldg(uspan + g);
        const float4 nu = __ldg(Nu + g);
        const int n  = t & 63;
        const int bl = t >> 6;             // 0..1
#pragma unroll
        for (int p = 0; p < 2; ++p) {
            const int bb = bl + 2 * p;     // 0..3
            const float4* base = ctrl + ((b0 + bb) * MCTRL + (us - 3)) * NCTRL + n;
            const float4 c0 = __ldg(base);
            const float4 c1 = __ldg(base + NCTRL);
            const float4 c2 = __ldg(base + 2 * NCTRL);
            const float4 c3 = __ldg(base + 3 * NCTRL);
            float4 a;
            a.x = nu.x * c0.x + nu.y * c1.x + nu.z * c2.x + nu.w * c3.x;
            a.y = nu.x * c0.y + nu.y * c1.y + nu.z * c2.y + nu.w * c3.y;
            a.z = nu.x * c0.z + nu.y * c1.z + nu.z * c2.z + nu.w * c3.z;
            a.w = nu.x * c0.w + nu.y * c1.w + nu.z * c2.w + nu.w * c3.w;
            Su[bb][n] = a;
        }
        if (t >= 124) Su[t - 124][NCTRL] = make_float4(0.f, 0.f, 0.f, 0.f);
    }
    __syncthreads();

    // ---- Stage B ----
    const int4 vsv = __ldg(vspan4 + t);
    const int j0 = vsv.x - 3;

    // 5-tap weights per h point (span delta vs first point is 0 or 1).
    float w[4][5];
    {
        const int h0 = t << 2;
        const int vd[4] = {0, vsv.y - vsv.x, vsv.z - vsv.x, vsv.w - vsv.x};
#pragma unroll
        for (int k = 0; k < 4; ++k) {
            const float4 nv = __ldg(Nv + h0 + k);
            const bool s = (vd[k] != 0);
            w[k][0] = s ? 0.0f : nv.x;
            w[k][1] = s ? nv.x : nv.y;
            w[k][2] = s ? nv.y : nv.z;
            w[k][3] = s ? nv.z : nv.w;
            w[k][4] = s ? nv.w : 0.0f;
        }
    }

    // Output: float4 index (b,g) row base + 3t; batch stride in float4 units.
    const int brow_stride = GRID_N * GRID_N * 3 / 4;   // 196608
    float4* o = out + (b0 * GRID_N + g) * (GRID_N * 3 / 4) + t * 3;

#pragma unroll
    for (int bb = 0; bb < BQ; ++bb) {
        const float4* SuB = Su[bb];
        const float4 q0 = SuB[j0];
        const float4 q1 = SuB[j0 + 1];
        const float4 q2 = SuB[j0 + 2];
        const float4 q3 = SuB[j0 + 3];
        const float4 q4 = SuB[j0 + 4];

        float r[12];
#pragma unroll
        for (int k = 0; k < 4; ++k) {
            const float X = w[k][0] * q0.x + w[k][1] * q1.x + w[k][2] * q2.x + w[k][3] * q3.x + w[k][4] * q4.x;
            const float Y = w[k][0] * q0.y + w[k][1] * q1.y + w[k][2] * q2.y + w[k][3] * q3.y + w[k][4] * q4.y;
            const float Z = w[k][0] * q0.z + w[k][1] * q1.z + w[k][2] * q2.z + w[k][3] * q3.z + w[k][4] * q4.z;
            const float W = w[k][0] * q0.w + w[k][1] * q1.w + w[k][2] * q2.w + w[k][3] * q3.w + w[k][4] * q4.w;
            const float inv = __fdividef(1.0f, W);
            r[k * 3 + 0] = X * inv;
            r[k * 3 + 1] = Y * inv;
            r[k * 3 + 2] = Z * inv;
        }

        o[0] = make_float4(r[0], r[1], r[2], r[3]);
        o[1] = make_float4(r[4], r[5], r[6], r[7]);
        o[2] = make_float4(r[8], r[9], r[10], r[11]);
        o += brow_stride;
    }
}

extern "C" void kernel_launch(void* const* d_in, const int* in_sizes, int n_in,
                              void* d_out, int out_size) {
    const float4* ctrl   = (const float4*)d_in[0];
    const int*    uspan  = (const int*)d_in[1];
    const int4*   vspan4 = (const int4*)d_in[2];
    const float4* Nu     = (const float4*)d_in[3];
    const float4* Nv     = (const float4*)d_in[4];

    const int B = in_sizes[0] / (MCTRL * NCTRL * 4);  // ctrl_pts elements = B*64*64*4

    dim3 grid(GRID_N, B / BQ);
    surf_eval_kernel<<<grid, 128>>>(ctrl, uspan, vspan4, Nu, Nv, (float4*)d_out);
}

// round 5
// speedup vs baseline: 1.0647x; 1.0172x over previous
#include <cuda_runtime.h>

// SurfEval: NURBS surface evaluation. B=8, M=N=64, P=Q=3, GRID=512, DIM=3.
// Block = (g, b) — the harness-best high-parallelism shape (4096 blocks, 16K warps).
// Stage A: u-contracted row Su[64] (float4) in smem, stored BANK-PADDED at
// slot f(j) = j + (j>>3) so Stage-B window reads (indices 8/16/24 apart across
// the warp) hit distinct banks -> conflict-free LDS.128.
// Stage B: each thread evaluates 4 consecutive h points from ONE 5-wide Su
// window + span-delta-shifted Nv weights; 3 aligned float4 stores.
// launch_bounds(128,10): 48 regs -> 10 CTAs/SM -> 40 warps/SM (62.5% occ).

#define GRID_N 512
#define MCTRL 64
#define NCTRL 64

// padded smem index: kills the j vs j+8/16/24 bank aliasing
__device__ __forceinline__ int fpad(int j) { return j + (j >> 3); }

__global__ __launch_bounds__(128, 10) void surf_eval_kernel(
    const float4* __restrict__ ctrl,   // (B, 64, 64) float4
    const int*    __restrict__ uspan,  // (512)
    const int4*   __restrict__ vspan4, // (512) ints viewed as (128) int4
    const float4* __restrict__ Nu,     // (512) float4
    const float4* __restrict__ Nv,     // (512) float4
    float4*       __restrict__ out)    // (B*512*512*3)/4 float4
{
    __shared__ float4 Su[73];          // f(64)=72 is the zero guard slot

    const int g = blockIdx.x;
    const int b = blockIdx.y;
    const int t = threadIdx.x;

    // ---- Stage A: Su[n] = sum_r Nu[g,r] * ctrl[b, us-3+r, n, :] ----
    if (t < NCTRL) {
        const int us = __ldg(uspan + g);
        const float4 nu = __ldg(Nu + g);
        const float4* base = ctrl + (b * MCTRL + (us - 3)) * NCTRL + t;
        const float4 c0 = __ldg(base);
        const float4 c1 = __ldg(base + NCTRL);
        const float4 c2 = __ldg(base + 2 * NCTRL);
        const float4 c3 = __ldg(base + 3 * NCTRL);
        float4 a;
        a.x = nu.x * c0.x + nu.y * c1.x + nu.z * c2.x + nu.w * c3.x;
        a.y = nu.x * c0.y + nu.y * c1.y + nu.z * c2.y + nu.w * c3.y;
        a.z = nu.x * c0.z + nu.y * c1.z + nu.z * c2.z + nu.w * c3.z;
        a.w = nu.x * c0.w + nu.y * c1.w + nu.z * c2.w + nu.w * c3.w;
        Su[fpad(t)] = a;
    } else if (t == NCTRL) {
        Su[72] = make_float4(0.f, 0.f, 0.f, 0.f);   // f(64) guard
    }
    __syncthreads();

    // ---- Stage B: 4 consecutive h points per thread, one 5-wide Su window ----
    const int4 vsv = __ldg(vspan4 + t);
    const int j0 = vsv.x - 3;

    const float4 q0 = Su[fpad(j0)];
    const float4 q1 = Su[fpad(j0 + 1)];
    const float4 q2 = Su[fpad(j0 + 2)];
    const float4 q3 = Su[fpad(j0 + 3)];
    const float4 q4 = Su[fpad(j0 + 4)];

    const int h0 = t << 2;
    const int vd[4] = {0, vsv.y - vsv.x, vsv.z - vsv.x, vsv.w - vsv.x};

    float r[12];
#pragma unroll
    for (int k = 0; k < 4; ++k) {
        const float4 nv = __ldg(Nv + h0 + k);
        const bool s = (vd[k] != 0);   // span delta (0 or 1, guaranteed)
        const float w0 = s ? 0.0f : nv.x;
        const float w1 = s ? nv.x : nv.y;
        const float w2 = s ? nv.y : nv.z;
        const float w3 = s ? nv.z : nv.w;
        const float w4 = s ? nv.w : 0.0f;

        const float X = w0 * q0.x + w1 * q1.x + w2 * q2.x + w3 * q3.x + w4 * q4.x;
        const float Y = w0 * q0.y + w1 * q1.y + w2 * q2.y + w3 * q3.y + w4 * q4.y;
        const float Z = w0 * q0.z + w1 * q1.z + w2 * q2.z + w3 * q3.z + w4 * q4.z;
        const float W = w0 * q0.w + w1 * q1.w + w2 * q2.w + w3 * q3.w + w4 * q4.w;

        const float inv = __fdividef(1.0f, W);
        r[k * 3 + 0] = X * inv;
        r[k * 3 + 1] = Y * inv;
        r[k * 3 + 2] = Z * inv;
    }

    // out row (b,g) is 384 aligned float4. Thread writes float4 [3t, 3t+2].
    float4* o = out + (b * GRID_N + g) * (GRID_N * 3 / 4) + t * 3;
    o[0] = make_float4(r[0], r[1], r[2], r[3]);
    o[1] = make_float4(r[4], r[5], r[6], r[7]);
    o[2] = make_float4(r[8], r[9], r[10], r[11]);
}

extern "C" void kernel_launch(void* const* d_in, const int* in_sizes, int n_in,
                              void* d_out, int out_size) {
    const float4* ctrl   = (const float4*)d_in[0];
    const int*    uspan  = (const int*)d_in[1];
    const int4*   vspan4 = (const int4*)d_in[2];
    const float4* Nu     = (const float4*)d_in[3];
    const float4* Nv     = (const float4*)d_in[4];

    const int B = in_sizes[0] / (MCTRL * NCTRL * 4);  // ctrl_pts elements = B*64*64*4

    dim3 grid(GRID_N, B);
    surf_eval_kernel<<<grid, 128>>>(ctrl, uspan, vspan4, Nu, Nv, (float4*)d_out);
}

// round 6
// speedup vs baseline: 1.0929x; 1.0265x over previous
#include <cuda_runtime.h>

// SurfEval: NURBS surface evaluation. B=8, M=N=64, P=Q=3, GRID=512, DIM=3.
// Block = (g-PAIR, b): 2048 blocks x 128 threads. Consecutive g almost always
// share uspan, so the pair-block loads ctrl once (uniform branch) and builds
// both Su rows; Stage-B vspan/Nv/weight work is computed once and reused for
// both g-lines (they depend only on h).

#define GRID_N 512
#define MCTRL 64
#define NCTRL 64

__global__ __launch_bounds__(128, 9) void surf_eval_kernel(
    const float4* __restrict__ ctrl,   // (B, 64, 64) float4
    const int*    __restrict__ uspan,  // (512)
    const int4*   __restrict__ vspan4, // (512) ints viewed as (128) int4
    const float4* __restrict__ Nu,     // (512) float4
    const float4* __restrict__ Nv,     // (512) float4
    float4*       __restrict__ out)    // (B*512*512*3)/4 float4
{
    __shared__ float4 Su[2][NCTRL + 1];   // [gg][n], +1 zero guard at n=64

    const int g0 = blockIdx.x << 1;
    const int b  = blockIdx.y;
    const int t  = threadIdx.x;

    // ---- Prefetch Stage-B inputs (independent of Su; overlaps Stage-A latency)
    const int4 vsv = __ldg(vspan4 + t);
    const int h0 = t << 2;
    const float4 nv0 = __ldg(Nv + h0);
    const float4 nv1 = __ldg(Nv + h0 + 1);
    const float4 nv2 = __ldg(Nv + h0 + 2);
    const float4 nv3 = __ldg(Nv + h0 + 3);

    // ---- Stage A: Su[gg][n] = sum_r Nu[g0+gg,r] * ctrl[b, us-3+r, n, :] ----
    {
        const int us0 = __ldg(uspan + g0);
        const int us1 = __ldg(uspan + g0 + 1);
        const int n    = t & 63;
        const int half = t >> 6;

        if (us0 == us1) {
            // common case (~88%): one set of ctrl loads feeds both g-lines
            if (half == 0) {
                const float4 nu0 = __ldg(Nu + g0);
                const float4 nu1 = __ldg(Nu + g0 + 1);
                const float4* base = ctrl + (b * MCTRL + (us0 - 3)) * NCTRL + n;
                const float4 c0 = __ldg(base);
                const float4 c1 = __ldg(base + NCTRL);
                const float4 c2 = __ldg(base + 2 * NCTRL);
                const float4 c3 = __ldg(base + 3 * NCTRL);
                float4 a;
                a.x = nu0.x * c0.x + nu0.y * c1.x + nu0.z * c2.x + nu0.w * c3.x;
                a.y = nu0.x * c0.y + nu0.y * c1.y + nu0.z * c2.y + nu0.w * c3.y;
                a.z = nu0.x * c0.z + nu0.y * c1.z + nu0.z * c2.z + nu0.w * c3.z;
                a.w = nu0.x * c0.w + nu0.y * c1.w + nu0.z * c2.w + nu0.w * c3.w;
                Su[0][n] = a;
                a.x = nu1.x * c0.x + nu1.y * c1.x + nu1.z * c2.x + nu1.w * c3.x;
                a.y = nu1.x * c0.y + nu1.y * c1.y + nu1.z * c2.y + nu1.w * c3.y;
                a.z = nu1.x * c0.z + nu1.y * c1.z + nu1.z * c2.z + nu1.w * c3.z;
                a.w = nu1.x * c0.w + nu1.y * c1.w + nu1.z * c2.w + nu1.w * c3.w;
                Su[1][n] = a;
            }
        } else {
            // spans differ: lower half builds g0's row, upper half g1's row
            const int    us = half ? us1 : us0;
            const float4 nu = __ldg(Nu + g0 + half);
            const float4* base = ctrl + (b * MCTRL + (us - 3)) * NCTRL + n;
            const float4 c0 = __ldg(base);
            const float4 c1 = __ldg(base + NCTRL);
            const float4 c2 = __ldg(base + 2 * NCTRL);
            const float4 c3 = __ldg(base + 3 * NCTRL);
            float4 a;
            a.x = nu.x * c0.x + nu.y * c1.x + nu.z * c2.x + nu.w * c3.x;
            a.y = nu.x * c0.y + nu.y * c1.y + nu.z * c2.y + nu.w * c3.y;
            a.z = nu.x * c0.z + nu.y * c1.z + nu.z * c2.z + nu.w * c3.z;
            a.w = nu.x * c0.w + nu.y * c1.w + nu.z * c2.w + nu.w * c3.w;
            Su[half][n] = a;
        }
        if (t == 124) Su[0][NCTRL] = make_float4(0.f, 0.f, 0.f, 0.f);
        if (t == 125) Su[1][NCTRL] = make_float4(0.f, 0.f, 0.f, 0.f);
    }
    __syncthreads();

    // ---- Stage B: weights once (depend only on h), reused for both g-lines
    const int j0 = vsv.x - 3;
    float w[4][5];
    {
        const float4 nvs[4] = {nv0, nv1, nv2, nv3};
        const int vd[4] = {0, vsv.y - vsv.x, vsv.z - vsv.x, vsv.w - vsv.x};
#pragma unroll
        for (int k = 0; k < 4; ++k) {
            const bool s = (vd[k] != 0);   // span delta 0 or 1
            w[k][0] = s ? 0.0f : nvs[k].x;
            w[k][1] = s ? nvs[k].x : nvs[k].y;
            w[k][2] = s ? nvs[k].y : nvs[k].z;
            w[k][3] = s ? nvs[k].z : nvs[k].w;
            w[k][4] = s ? nvs[k].w : 0.0f;
        }
    }

    float4* o = out + (b * GRID_N + g0) * (GRID_N * 3 / 4) + t * 3;
    const int grow = GRID_N * 3 / 4;   // float4 stride between g-lines

#pragma unroll
    for (int gg = 0; gg < 2; ++gg) {
        const float4* SuG = Su[gg];
        const float4 q0 = SuG[j0];
        const float4 q1 = SuG[j0 + 1];
        const float4 q2 = SuG[j0 + 2];
        const float4 q3 = SuG[j0 + 3];
        const float4 q4 = SuG[j0 + 4];

        float r[12];
#pragma unroll
        for (int k = 0; k < 4; ++k) {
            const float X = w[k][0] * q0.x + w[k][1] * q1.x + w[k][2] * q2.x + w[k][3] * q3.x + w[k][4] * q4.x;
            const float Y = w[k][0] * q0.y + w[k][1] * q1.y + w[k][2] * q2.y + w[k][3] * q3.y + w[k][4] * q4.y;
            const float Z = w[k][0] * q0.z + w[k][1] * q1.z + w[k][2] * q2.z + w[k][3] * q3.z + w[k][4] * q4.z;
            const float W = w[k][0] * q0.w + w[k][1] * q1.w + w[k][2] * q2.w + w[k][3] * q3.w + w[k][4] * q4.w;
            const float inv = __fdividef(1.0f, W);
            r[k * 3 + 0] = X * inv;
            r[k * 3 + 1] = Y * inv;
            r[k * 3 + 2] = Z * inv;
        }
        o[0] = make_float4(r[0], r[1], r[2], r[3]);
        o[1] = make_float4(r[4], r[5], r[6], r[7]);
        o[2] = make_float4(r[8], r[9], r[10], r[11]);
        o += grow;
    }
}

extern "C" void kernel_launch(void* const* d_in, const int* in_sizes, int n_in,
                              void* d_out, int out_size) {
    const float4* ctrl   = (const float4*)d_in[0];
    const int*    uspan  = (const int*)d_in[1];
    const int4*   vspan4 = (const int4*)d_in[2];
    const float4* Nu     = (const float4*)d_in[3];
    const float4* Nv     = (const float4*)d_in[4];

    const int B = in_sizes[0] / (MCTRL * NCTRL * 4);  // ctrl_pts elements = B*64*64*4

    dim3 grid(GRID_N / 2, B);
    surf_eval_kernel<<<grid, 128>>>(ctrl, uspan, vspan4, Nu, Nv, (float4*)d_out);
}